// round 1
// baseline (speedup 1.0000x reference)
#include <cuda_runtime.h>
#include <math.h>

// Problem shape (fixed by the dataset)
#define BB 2
#define NN 8192
#define DD 256

// Scratch for tangent-space vectors (16 MB) — static __device__ per harness rules
__device__ float g_tangent[(size_t)BB * NN * DD];

// ---------------------------------------------------------------------------
// Kernel 1: x_tangent = logmap0(x) = artanh(min(||x||,1-1e-7)) * x / max(||x||,1e-15)
// One 256-thread block per row (D = 256).
// ---------------------------------------------------------------------------
__global__ void tangent_kernel(const float* __restrict__ x) {
    const int row = blockIdx.x;           // 0 .. B*N-1
    const int t = threadIdx.x;            // 0 .. 255
    const size_t base = (size_t)row * DD;
    const float v = x[base + t];

    // block-wide sum of squares
    float s = v * v;
    #pragma unroll
    for (int o = 16; o > 0; o >>= 1) s += __shfl_xor_sync(0xffffffffu, s, o);

    __shared__ float ws[8];
    __shared__ float scale_s;
    const int w = t >> 5, l = t & 31;
    if (l == 0) ws[w] = s;
    __syncthreads();
    if (t == 0) {
        float tot = 0.f;
        #pragma unroll
        for (int i = 0; i < 8; i++) tot += ws[i];
        float n = fmaxf(sqrtf(tot), 1e-15f);
        float a = fminf(n, 1.0f - 1e-7f);     // artanh input clip (n >= 0)
        scale_s = atanhf(a) / n;
    }
    __syncthreads();
    g_tangent[base + t] = v * scale_s;
}

// ---------------------------------------------------------------------------
// Kernel 2: out = project(expmap0(adj @ x_tangent))
// BM=128, BN=256 (full D per CTA -> adj read exactly once, row-norm epilogue
// stays intra-warp), BK=16, 512 threads, 8x8 per-thread microtile.
// ---------------------------------------------------------------------------
#define BM 128
#define BN 256
#define BK 16

__global__ __launch_bounds__(512, 1)
void hypagg_gemm(const float* __restrict__ adj, float* __restrict__ out) {
    __shared__ float As[BK][BM];   // A stored transposed: As[k][m]
    __shared__ float Bs[BK][BN];

    const int b  = blockIdx.y;
    const int i0 = blockIdx.x * BM;
    const int tid = threadIdx.x;
    const int tx = tid & 31;   // N direction: cols tx*8 .. tx*8+7
    const int ty = tid >> 5;   // M direction: rows ty*8 .. ty*8+7  (== warp id)

    const float* __restrict__ adjB = adj + (size_t)b * NN * NN;
    const float* __restrict__ tg   = g_tangent + (size_t)b * NN * DD;

    float acc[8][8];
    #pragma unroll
    for (int i = 0; i < 8; i++)
        #pragma unroll
        for (int j = 0; j < 8; j++) acc[i][j] = 0.f;

    // Global->reg load indices
    const int a_row = tid >> 2;           // 0..127
    const int a_k   = (tid & 3) * 4;      // 0,4,8,12
    const int b_row = tid >> 6;           // 0..7 (and +8 for the second half)
    const int b_col = (tid & 63) * 4;     // 0..252

    // Preload K-tile 0 into registers
    float4 av  = *(const float4*)(adjB + (size_t)(i0 + a_row) * NN + a_k);
    float4 bv0 = *(const float4*)(tg + (size_t)(b_row)     * DD + b_col);
    float4 bv1 = *(const float4*)(tg + (size_t)(b_row + 8) * DD + b_col);

    const int NKT = NN / BK;   // 512
    for (int kt = 0; kt < NKT; kt++) {
        // regs -> smem
        As[a_k + 0][a_row] = av.x;
        As[a_k + 1][a_row] = av.y;
        As[a_k + 2][a_row] = av.z;
        As[a_k + 3][a_row] = av.w;
        *(float4*)&Bs[b_row][b_col]     = bv0;
        *(float4*)&Bs[b_row + 8][b_col] = bv1;
        __syncthreads();

        // prefetch next tile into regs (hidden under compute)
        if (kt + 1 < NKT) {
            const int k0 = (kt + 1) * BK;
            av  = *(const float4*)(adjB + (size_t)(i0 + a_row) * NN + k0 + a_k);
            bv0 = *(const float4*)(tg + (size_t)(k0 + b_row)     * DD + b_col);
            bv1 = *(const float4*)(tg + (size_t)(k0 + b_row + 8) * DD + b_col);
        }

        #pragma unroll
        for (int k = 0; k < BK; k++) {
            float4 a0 = *(const float4*)&As[k][ty * 8];
            float4 a1 = *(const float4*)&As[k][ty * 8 + 4];
            float4 c0 = *(const float4*)&Bs[k][tx * 8];
            float4 c1 = *(const float4*)&Bs[k][tx * 8 + 4];
            float ar[8] = {a0.x, a0.y, a0.z, a0.w, a1.x, a1.y, a1.z, a1.w};
            float br[8] = {c0.x, c0.y, c0.z, c0.w, c1.x, c1.y, c1.z, c1.w};
            #pragma unroll
            for (int m = 0; m < 8; m++)
                #pragma unroll
                for (int n = 0; n < 8; n++)
                    acc[m][n] = fmaf(ar[m], br[n], acc[m][n]);
        }
        __syncthreads();
    }

    // Epilogue: per-row expmap0 + project. Each row of 256 values lives in one
    // warp (same ty), 8 cols per lane -> warp-shuffle row reduction.
    const float maxnorm = 1.0f - 4e-3f;   // (1 - BALL_EPS)/sqrt(c)
    #pragma unroll
    for (int m = 0; m < 8; m++) {
        float ss = 0.f;
        #pragma unroll
        for (int n = 0; n < 8; n++) ss = fmaf(acc[m][n], acc[m][n], ss);
        #pragma unroll
        for (int o = 16; o > 0; o >>= 1) ss += __shfl_xor_sync(0xffffffffu, ss, o);

        float nrm = fmaxf(sqrtf(ss), 1e-15f);
        float th  = tanhf(nrm);
        float sc  = th / nrm;                       // expmap0 scale
        if (th > maxnorm) sc *= maxnorm / th;       // project (||y|| == th)

        const int row = i0 + ty * 8 + m;
        float* op = out + ((size_t)b * NN + row) * DD + tx * 8;
        float4 o0 = make_float4(acc[m][0] * sc, acc[m][1] * sc,
                                acc[m][2] * sc, acc[m][3] * sc);
        float4 o1 = make_float4(acc[m][4] * sc, acc[m][5] * sc,
                                acc[m][6] * sc, acc[m][7] * sc);
        *(float4*)(op)     = o0;
        *(float4*)(op + 4) = o1;
    }
}

// ---------------------------------------------------------------------------
extern "C" void kernel_launch(void* const* d_in, const int* in_sizes, int n_in,
                              void* d_out, int out_size) {
    // x has B*N*D = 4,194,304 elems; adj has B*N*N = 134,217,728. Identify by size.
    const float* x;
    const float* adj;
    if (in_sizes[0] < in_sizes[1]) { x = (const float*)d_in[0]; adj = (const float*)d_in[1]; }
    else                           { x = (const float*)d_in[1]; adj = (const float*)d_in[0]; }
    float* out = (float*)d_out;

    tangent_kernel<<<BB * NN, 256>>>(x);
    dim3 grid(NN / BM, BB);
    hypagg_gemm<<<grid, 512>>>(adj, out);
}

// round 3
// speedup vs baseline: 8.9396x; 8.9396x over previous
#include <cuda_runtime.h>
#include <math.h>
#include <stdint.h>

// Problem shape (fixed)
#define BB 2
#define NN 8192
#define DD 256

// Scratch: tangent vectors, tf32-rounded.
//  g_t  : row-major  [b][n][d]   (B operand for mma.sync fallback)
//  g_tT : transposed [b][d][n]   (K-major B operand for tcgen05)
__device__ float g_t [(size_t)BB * NN * DD];
__device__ float g_tT[(size_t)BB * DD * NN];

#define SW128(o) ((o) ^ ((((o) >> 3)) & 0x70))

// truncation-bias compensation for tf32-truncated adj operand (2^-11 * ln2)
#define CORR 1.000338f

// ===========================================================================
// Kernel 1: logmap0, round-to-nearest tf32, write both layouts.
// ===========================================================================
__global__ __launch_bounds__(256)
void tangent_kernel(const float* __restrict__ x) {
    __shared__ float sm[32 * 257];
    __shared__ float s_scale[32];

    const int blk = blockIdx.x;                // 0 .. 511
    const int b   = blk >> 8;
    const int n0  = (blk & 255) * 32;
    const int tid = threadIdx.x;

    const float* __restrict__ xb = x + ((size_t)b * NN + n0) * DD;

    #pragma unroll
    for (int i = 0; i < 32; i++) {
        int f = i * 256 + tid;
        int r = f >> 8, d = f & 255;
        sm[r * 257 + d] = xb[(size_t)r * DD + d];
    }
    __syncthreads();

    const int w = tid >> 5, l = tid & 31;
    #pragma unroll
    for (int q = 0; q < 4; q++) {
        int r = w * 4 + q;
        float s = 0.f;
        #pragma unroll
        for (int j = 0; j < 8; j++) {
            float v = sm[r * 257 + l + 32 * j];
            s = fmaf(v, v, s);
        }
        #pragma unroll
        for (int o = 16; o > 0; o >>= 1) s += __shfl_xor_sync(0xffffffffu, s, o);
        if (l == 0) {
            float n = sqrtf(s);
            float a = fminf(n, 1.0f - 1e-7f);
            s_scale[r] = atanhf(a) / fmaxf(n, 1e-15f);
        }
    }
    __syncthreads();

    // row-major write (coalesced over d)
    float* __restrict__ tb = g_t + ((size_t)b * NN + n0) * DD;
    #pragma unroll
    for (int i = 0; i < 32; i++) {
        float v = sm[i * 257 + tid] * s_scale[i];
        uint32_t u;
        asm("cvt.rna.tf32.f32 %0, %1;" : "=r"(u) : "f"(v));
        tb[(size_t)i * DD + tid] = __uint_as_float(u);
    }

    // transposed write (coalesced over n)
    float* __restrict__ tTb = g_tT + (size_t)b * DD * NN;
    #pragma unroll
    for (int i = 0; i < 32; i++) {
        int f = i * 256 + tid;
        int d = f >> 5, n_off = f & 31;
        float v = sm[n_off * 257 + d] * s_scale[n_off];
        uint32_t u;
        asm("cvt.rna.tf32.f32 %0, %1;" : "=r"(u) : "f"(v));
        tTb[(size_t)d * NN + n0 + n_off] = __uint_as_float(u);
    }
}

// ===========================================================================
// Shared helpers (arch-neutral)
// ===========================================================================
static __device__ __forceinline__ uint32_t smem_u32(const void* p) {
    uint32_t a;
    asm("{ .reg .u64 t; cvta.to.shared.u64 t, %1; cvt.u32.u64 %0, t; }"
        : "=r"(a) : "l"(p));
    return a;
}
static __device__ __forceinline__ void cp16(uint32_t dst, const void* src) {
    asm volatile("cp.async.cg.shared.global [%0], [%1], 16;"
                 :: "r"(dst), "l"(src) : "memory");
}

// ---- tcgen05 config (sm_103a path) ----
#define NKT   (NN / 32)          // 256 K-tiles of BK=32
#define SOFF_A 1024
#define ASTG  (128 * 128)
#define SOFF_B (1024 + 3 * ASTG)
#define BSTG  (256 * 128)
#define TC_SMEM (SOFF_B + 3 * BSTG)      // 148480
#define MB_OFF(i) (16 + 8 * (i))
#define IDESC 0x08400910u
#define DESC_BASE ((2ULL << 61) | (1ULL << 46) | (64ULL << 32) | (1ULL << 16))

// ---- mma.sync fallback config (plain sm_103 path) ----
#define FB_ASTR 36
#define FB_BSTR 264
#define FB_ABYTES (128 * FB_ASTR * 4)    // 18432
#define FB_BBYTES (32 * FB_BSTR * 4)     // 33792
#define FB_STAGE  (FB_ABYTES + FB_BBYTES)// 52224
#define FB_SMEM   (3 * FB_STAGE)         // 156672

#define SMEM_DYN  (FB_SMEM > TC_SMEM ? FB_SMEM : TC_SMEM)

#if defined(__CUDA_ARCH__) && defined(__CUDA_ARCH_FEAT_SM103_ALL)
// tcgen05-only helpers
static __device__ __forceinline__ uint32_t elect_one() {
    uint32_t p;
    asm volatile("{\n\t.reg .pred p;\n\t"
                 "elect.sync _|p, 0xFFFFFFFF;\n\t"
                 "selp.b32 %0, 1, 0, p;\n\t}" : "=r"(p));
    return p;
}
static __device__ __forceinline__ void mbar_init(uint32_t mbar, uint32_t cnt) {
    asm volatile("mbarrier.init.shared.b64 [%0], %1;" :: "r"(mbar), "r"(cnt) : "memory");
}
static __device__ __forceinline__ void mbar_wait(uint32_t mbar, uint32_t parity) {
    asm volatile(
        "{\n\t.reg .pred P;\n\t"
        "W%=:\n\t"
        "mbarrier.try_wait.parity.acquire.cta.shared::cta.b64 P, [%0], %1, 0x989680;\n\t"
        "@P bra.uni D%=;\n\t"
        "bra.uni W%=;\n\t"
        "D%=:\n\t}"
        :: "r"(mbar), "r"(parity) : "memory");
}
static __device__ __forceinline__ void mma_tf32(uint32_t d_tmem, uint64_t a_desc,
                                                uint64_t b_desc, uint32_t en) {
    asm volatile(
        "{\n\t.reg .pred p;\n\t"
        "setp.ne.u32 p, %5, 0;\n\t"
        "tcgen05.mma.cta_group::1.kind::tf32 [%0], %1, %2, %3, {%4,%4,%4,%4}, p;\n\t}"
        :: "r"(d_tmem), "l"(a_desc), "l"(b_desc), "r"(IDESC), "r"(0u), "r"(en)
        : "memory");
}
static __device__ __forceinline__ void tmem_commit(uint32_t mbar) {
    asm volatile(
        "tcgen05.commit.cta_group::1.mbarrier::arrive::one.shared::cluster.b64 [%0];"
        :: "r"(mbar) : "memory");
}
static __device__ __forceinline__ uint64_t mk_desc(uint32_t addr) {
    return DESC_BASE | (uint64_t)((addr >> 4) & 0x3FFF);
}
#endif

// ===========================================================================
// Kernel 2: out = project(expmap0(adj @ t)), tensor-core GEMM.
// Grid 128 = 64 M-tiles x 2 batches. 512 threads. Dynamic smem SMEM_DYN.
// ===========================================================================
__global__ __launch_bounds__(512, 1)
void hypagg_tc(const float* __restrict__ adj, float* __restrict__ out) {
#if defined(__CUDA_ARCH__) && defined(__CUDA_ARCH_FEAT_SM103_ALL)
    // =================== tcgen05 tf32 path (sm_103a) =====================
    extern __shared__ char smem[];
    const uint32_t smb = smem_u32(smem);
    const int tid = threadIdx.x;
    const int wid = tid >> 5;
    const int lane = tid & 31;

    const int blk = blockIdx.x;
    const int b   = blk >> 6;
    const int i0  = (blk & 63) * 128;

    const float* __restrict__ adjB = adj + (size_t)b * NN * NN;
    const float* __restrict__ tTb  = g_tT + (size_t)b * DD * NN;

    const char* gp[6];
    uint32_t sb_off[6], sstep[6];
    #pragma unroll
    for (int j = 0; j < 6; j++) {
        int c = tid + j * 512;
        if (c < 1024) {
            int row = c >> 3, k4 = c & 7;
            gp[j] = (const char*)(adjB + (size_t)(i0 + row) * NN) + k4 * 16;
            sb_off[j] = SOFF_A + SW128(row * 128 + k4 * 16);
            sstep[j]  = ASTG;
        } else {
            int cc = c - 1024;
            int d = cc >> 3, k4 = cc & 7;
            gp[j] = (const char*)(tTb + (size_t)d * NN) + k4 * 16;
            sb_off[j] = SOFF_B + SW128(d * 128 + k4 * 16);
            sstep[j]  = BSTG;
        }
    }

    if (tid == 0) {
        mbar_init(smb + MB_OFF(0), 1);
        mbar_init(smb + MB_OFF(1), 1);
        mbar_init(smb + MB_OFF(2), 1);
    }
    if (wid == 0) {
        asm volatile("tcgen05.alloc.cta_group::1.sync.aligned.shared::cta.b32 [%0], %1;"
                     :: "r"(smb), "r"(256u) : "memory");
    }
    __syncthreads();
    uint32_t tmem;
    asm volatile("ld.shared.b32 %0, [%1];" : "=r"(tmem) : "r"(smb));

    #pragma unroll
    for (int t0 = 0; t0 < 2; t0++) {
        #pragma unroll
        for (int j = 0; j < 6; j++)
            cp16(smb + sb_off[j] + t0 * sstep[j], gp[j] + (size_t)t0 * 128);
        asm volatile("cp.async.commit_group;" ::: "memory");
    }

    int ph[3] = {0, 0, 0};
    int slot = 0, slotL = 2;

    for (int kt = 0; kt < NKT; kt++) {
        if (kt <= NKT - 3) {
            if (kt >= 1) { mbar_wait(smb + MB_OFF(slotL), ph[slotL]); ph[slotL] ^= 1; }
            #pragma unroll
            for (int j = 0; j < 6; j++)
                cp16(smb + sb_off[j] + slotL * sstep[j], gp[j] + (size_t)(kt + 2) * 128);
            asm volatile("cp.async.commit_group;" ::: "memory");
        }
        if      (kt <  NKT - 2) asm volatile("cp.async.wait_group 2;" ::: "memory");
        else if (kt == NKT - 2) asm volatile("cp.async.wait_group 1;" ::: "memory");
        else                    asm volatile("cp.async.wait_group 0;" ::: "memory");
        __syncthreads();

        if (wid == 0) {
            if (elect_one()) {
                asm volatile("fence.proxy.async.shared::cta;" ::: "memory");
                uint64_t ad = mk_desc(smb + SOFF_A + slot * ASTG);
                uint64_t bd = mk_desc(smb + SOFF_B + slot * BSTG);
                #pragma unroll
                for (int ks = 0; ks < 4; ks++)
                    mma_tf32(tmem, ad + 2 * ks, bd + 2 * ks,
                             (kt == 0 && ks == 0) ? 0u : 1u);
                tmem_commit(smb + MB_OFF(slot));
            }
        }
        slot  = (slot  == 2) ? 0 : slot + 1;
        slotL = (slotL == 2) ? 0 : slotL + 1;
    }

    mbar_wait(smb + MB_OFF((NKT - 1) % 3), ph[(NKT - 1) % 3]);
    asm volatile("tcgen05.fence::after_thread_sync;" ::: "memory");
    __syncthreads();

    if (wid < 4) {
        const int grow = b * NN + i0 + wid * 32 + lane;
        float* __restrict__ op = out + (size_t)grow * DD;

        float ss = 0.f;
        #pragma unroll
        for (int c = 0; c < 8; c++) {
            uint32_t r[32];
            asm volatile(
                "tcgen05.ld.sync.aligned.32x32b.x32.b32 "
                "{%0,%1,%2,%3,%4,%5,%6,%7,%8,%9,%10,%11,%12,%13,%14,%15,"
                "%16,%17,%18,%19,%20,%21,%22,%23,%24,%25,%26,%27,%28,%29,%30,%31}, [%32];"
                : "=r"(r[0]),"=r"(r[1]),"=r"(r[2]),"=r"(r[3]),"=r"(r[4]),"=r"(r[5]),"=r"(r[6]),"=r"(r[7]),
                  "=r"(r[8]),"=r"(r[9]),"=r"(r[10]),"=r"(r[11]),"=r"(r[12]),"=r"(r[13]),"=r"(r[14]),"=r"(r[15]),
                  "=r"(r[16]),"=r"(r[17]),"=r"(r[18]),"=r"(r[19]),"=r"(r[20]),"=r"(r[21]),"=r"(r[22]),"=r"(r[23]),
                  "=r"(r[24]),"=r"(r[25]),"=r"(r[26]),"=r"(r[27]),"=r"(r[28]),"=r"(r[29]),"=r"(r[30]),"=r"(r[31])
                : "r"(tmem + c * 32));
            asm volatile("tcgen05.wait::ld.sync.aligned;" ::: "memory");
            #pragma unroll
            for (int i = 0; i < 32; i++) {
                float v = __uint_as_float(r[i]);
                ss = fmaf(v, v, ss);
            }
        }
        const float nr = fmaxf(sqrtf(ss), 1e-15f);
        const float n  = nr * CORR;
        const float th = tanhf(n);
        const float sc = (th > 1.0f - 4e-3f) ? ((1.0f - 4e-3f) / nr) : (th / nr);

        #pragma unroll
        for (int c = 0; c < 8; c++) {
            uint32_t r[32];
            asm volatile(
                "tcgen05.ld.sync.aligned.32x32b.x32.b32 "
                "{%0,%1,%2,%3,%4,%5,%6,%7,%8,%9,%10,%11,%12,%13,%14,%15,"
                "%16,%17,%18,%19,%20,%21,%22,%23,%24,%25,%26,%27,%28,%29,%30,%31}, [%32];"
                : "=r"(r[0]),"=r"(r[1]),"=r"(r[2]),"=r"(r[3]),"=r"(r[4]),"=r"(r[5]),"=r"(r[6]),"=r"(r[7]),
                  "=r"(r[8]),"=r"(r[9]),"=r"(r[10]),"=r"(r[11]),"=r"(r[12]),"=r"(r[13]),"=r"(r[14]),"=r"(r[15]),
                  "=r"(r[16]),"=r"(r[17]),"=r"(r[18]),"=r"(r[19]),"=r"(r[20]),"=r"(r[21]),"=r"(r[22]),"=r"(r[23]),
                  "=r"(r[24]),"=r"(r[25]),"=r"(r[26]),"=r"(r[27]),"=r"(r[28]),"=r"(r[29]),"=r"(r[30]),"=r"(r[31])
                : "r"(tmem + c * 32));
            asm volatile("tcgen05.wait::ld.sync.aligned;" ::: "memory");
            #pragma unroll
            for (int q = 0; q < 8; q++) {
                float4 v4;
                v4.x = __uint_as_float(r[q * 4 + 0]) * sc;
                v4.y = __uint_as_float(r[q * 4 + 1]) * sc;
                v4.z = __uint_as_float(r[q * 4 + 2]) * sc;
                v4.w = __uint_as_float(r[q * 4 + 3]) * sc;
                *(float4*)(op + c * 32 + q * 4) = v4;
            }
        }
    }

    __syncthreads();
    if (wid == 0) {
        asm volatile("tcgen05.dealloc.cta_group::1.sync.aligned.b32 %0, %1;"
                     :: "r"(tmem), "r"(256u));
    }

#elif defined(__CUDA_ARCH__)
    // =================== mma.sync tf32 fallback (sm_103) =================
    extern __shared__ char smem[];
    const uint32_t smb = smem_u32(smem);
    const int tid  = threadIdx.x;
    const int wrp  = tid >> 5;
    const int lane = tid & 31;
    const int wm   = wrp & 1;          // 2 M-blocks of 64
    const int wn   = wrp >> 1;         // 8 N-blocks of 32
    const int g    = lane >> 2;        // 0..7
    const int tig  = lane & 3;         // 0..3

    const int blk = blockIdx.x;
    const int b   = blk >> 6;
    const int i0  = (blk & 63) * 128;

    const float* __restrict__ adjB = adj + (size_t)b * NN * NN;
    const float* __restrict__ tg   = g_t + (size_t)b * NN * DD;

    // load slots: A = 2 chunks/thread, B = 4 chunks/thread (16B each)
    const char* gpA[2]; uint32_t soA[2];
    const char* gpB[4]; uint32_t soB[4];
    #pragma unroll
    for (int j = 0; j < 2; j++) {
        int c = tid + j * 512;               // 0..1023
        int row = c >> 3, kc = c & 7;
        gpA[j] = (const char*)(adjB + (size_t)(i0 + row) * NN) + kc * 16;
        soA[j] = row * (FB_ASTR * 4) + kc * 16;
    }
    #pragma unroll
    for (int j = 0; j < 4; j++) {
        int c = tid + j * 512;               // 0..2047
        int row = c >> 6, nc = c & 63;
        gpB[j] = (const char*)(tg + (size_t)row * DD) + nc * 16;
        soB[j] = FB_ABYTES + row * (FB_BSTR * 4) + nc * 16;
    }

    float cacc[4][4][4];
    #pragma unroll
    for (int i = 0; i < 4; i++)
        #pragma unroll
        for (int j = 0; j < 4; j++)
            #pragma unroll
            for (int q = 0; q < 4; q++) cacc[i][j][q] = 0.f;

    // prologue: tiles 0,1 -> slots 0,1
    #pragma unroll
    for (int t0 = 0; t0 < 2; t0++) {
        #pragma unroll
        for (int j = 0; j < 2; j++)
            cp16(smb + t0 * FB_STAGE + soA[j], gpA[j] + (size_t)t0 * 128);
        #pragma unroll
        for (int j = 0; j < 4; j++)
            cp16(smb + t0 * FB_STAGE + soB[j], gpB[j] + (size_t)t0 * 32768);
        asm volatile("cp.async.commit_group;" ::: "memory");
    }

    for (int kt = 0; kt < NKT; kt++) {
        const int slot  = kt % 3;
        const int slotL = (kt + 2) % 3;
        if (kt + 2 < NKT) {
            #pragma unroll
            for (int j = 0; j < 2; j++)
                cp16(smb + slotL * FB_STAGE + soA[j], gpA[j] + (size_t)(kt + 2) * 128);
            #pragma unroll
            for (int j = 0; j < 4; j++)
                cp16(smb + slotL * FB_STAGE + soB[j], gpB[j] + (size_t)(kt + 2) * 32768);
            asm volatile("cp.async.commit_group;" ::: "memory");
        }
        if      (kt <  NKT - 2) asm volatile("cp.async.wait_group 2;" ::: "memory");
        else if (kt == NKT - 2) asm volatile("cp.async.wait_group 1;" ::: "memory");
        else                    asm volatile("cp.async.wait_group 0;" ::: "memory");
        __syncthreads();

        const float* As = (const float*)(smem + slot * FB_STAGE);
        const float* Bs = (const float*)(smem + slot * FB_STAGE + FB_ABYTES);

        #pragma unroll
        for (int ks = 0; ks < 4; ks++) {
            const int kk = ks * 8;
            uint32_t a[4][4], bb[4][2];
            #pragma unroll
            for (int i = 0; i < 4; i++) {
                int r0 = wm * 64 + i * 16 + g;
                a[i][0] = __float_as_uint(As[(r0)     * FB_ASTR + kk + tig]);
                a[i][1] = __float_as_uint(As[(r0 + 8) * FB_ASTR + kk + tig]);
                a[i][2] = __float_as_uint(As[(r0)     * FB_ASTR + kk + tig + 4]);
                a[i][3] = __float_as_uint(As[(r0 + 8) * FB_ASTR + kk + tig + 4]);
            }
            #pragma unroll
            for (int j = 0; j < 4; j++) {
                int nn = wn * 32 + j * 8 + g;
                bb[j][0] = __float_as_uint(Bs[(kk + tig)     * FB_BSTR + nn]);
                bb[j][1] = __float_as_uint(Bs[(kk + tig + 4) * FB_BSTR + nn]);
            }
            #pragma unroll
            for (int i = 0; i < 4; i++)
                #pragma unroll
                for (int j = 0; j < 4; j++)
                    asm volatile(
                        "mma.sync.aligned.m16n8k8.row.col.f32.tf32.tf32.f32 "
                        "{%0,%1,%2,%3}, {%4,%5,%6,%7}, {%8,%9}, {%0,%1,%2,%3};"
                        : "+f"(cacc[i][j][0]), "+f"(cacc[i][j][1]),
                          "+f"(cacc[i][j][2]), "+f"(cacc[i][j][3])
                        : "r"(a[i][0]), "r"(a[i][1]), "r"(a[i][2]), "r"(a[i][3]),
                          "r"(bb[j][0]), "r"(bb[j][1]));
        }
        __syncthreads();
    }

    // ---- epilogue: cross-warp row norms via smem ----
    float* red = (float*)smem;          // [8][128] partials
    float* scs = (float*)smem + 1024;   // [128] per-row scales

    #pragma unroll
    for (int i = 0; i < 4; i++) {
        int r0 = wm * 64 + i * 16 + g;
        float ss0 = 0.f, ss1 = 0.f;
        #pragma unroll
        for (int j = 0; j < 4; j++) {
            ss0 = fmaf(cacc[i][j][0], cacc[i][j][0], ss0);
            ss0 = fmaf(cacc[i][j][1], cacc[i][j][1], ss0);
            ss1 = fmaf(cacc[i][j][2], cacc[i][j][2], ss1);
            ss1 = fmaf(cacc[i][j][3], cacc[i][j][3], ss1);
        }
        ss0 += __shfl_xor_sync(0xffffffffu, ss0, 1);
        ss0 += __shfl_xor_sync(0xffffffffu, ss0, 2);
        ss1 += __shfl_xor_sync(0xffffffffu, ss1, 1);
        ss1 += __shfl_xor_sync(0xffffffffu, ss1, 2);
        if (tig == 0) {
            red[wn * 128 + r0]     = ss0;
            red[wn * 128 + r0 + 8] = ss1;
        }
    }
    __syncthreads();

    if (tid < 128) {
        float tot = 0.f;
        #pragma unroll
        for (int p = 0; p < 8; p++) tot += red[p * 128 + tid];
        float nr = fmaxf(sqrtf(tot), 1e-15f);
        float n  = nr * CORR;
        float th = tanhf(n);
        scs[tid] = (th > 1.0f - 4e-3f) ? ((1.0f - 4e-3f) / nr) : (th / nr);
    }
    __syncthreads();

    #pragma unroll
    for (int i = 0; i < 4; i++) {
        int r0 = wm * 64 + i * 16 + g;
        float s0 = scs[r0], s1 = scs[r0 + 8];
        float* op0 = out + ((size_t)(b * NN + i0 + r0))     * DD + wn * 32 + 2 * tig;
        float* op1 = out + ((size_t)(b * NN + i0 + r0 + 8)) * DD + wn * 32 + 2 * tig;
        #pragma unroll
        for (int j = 0; j < 4; j++) {
            float2 v0 = make_float2(cacc[i][j][0] * s0, cacc[i][j][1] * s0);
            float2 v1 = make_float2(cacc[i][j][2] * s1, cacc[i][j][3] * s1);
            *(float2*)(op0 + j * 8) = v0;
            *(float2*)(op1 + j * 8) = v1;
        }
    }
#endif
}

// ===========================================================================
extern "C" void kernel_launch(void* const* d_in, const int* in_sizes, int n_in,
                              void* d_out, int out_size) {
    const float* x;
    const float* adj;
    if (in_sizes[0] < in_sizes[1]) { x = (const float*)d_in[0]; adj = (const float*)d_in[1]; }
    else                           { x = (const float*)d_in[1]; adj = (const float*)d_in[0]; }
    float* out = (float*)d_out;

    cudaFuncSetAttribute(hypagg_tc, cudaFuncAttributeMaxDynamicSharedMemorySize, SMEM_DYN);

    tangent_kernel<<<BB * NN / 32, 256>>>(x);
    hypagg_tc<<<128, 512, SMEM_DYN>>>(adj, out);
}